// round 3
// baseline (speedup 1.0000x reference)
#include <cuda_runtime.h>
#include <cuda_bf16.h>
#include <cstdint>

// ============================================================================
// Problem constants
// ============================================================================
#define BATCH    4096
#define INPUTDIM 256
#define OUTDIM   256
#define GRIDSZ   64
#define KDIM     32768          // k = cs*16384 + i*64 + g
#define NCHUNK   512            // K chunks of 64 (one (cs,i) pair each)
#define MTILE    128
#define NTILE    64
#define MTILES   (BATCH / MTILE)   // 32
#define NTILES   (OUTDIM / NTILE)  // 4

// SMEM stage layout: padded rows of 72 bf16 = 144 B (bank-conflict-free frags)
#define ROWB        144
#define A_BYTES     (128 * ROWB)            // 18432
#define B_BYTES     (64 * ROWB)             // 9216
#define OFF_AHI     0
#define OFF_ALO     (A_BYTES)
#define OFF_BHI     (2 * A_BYTES)
#define OFF_BLO     (2 * A_BYTES + B_BYTES)
#define STAGE_BYTES (2 * A_BYTES + 2 * B_BYTES)   // 55296
#define NSTAGE      3
#define SMEM_BYTES  (NSTAGE * STAGE_BYTES)        // 165888

// ============================================================================
// Scratch (device globals — no allocation allowed)
// ============================================================================
__device__ uint4 g_Bhi[(size_t)OUTDIM * KDIM / 8];   // bf16 [256][32768] hi
__device__ uint4 g_Blo[(size_t)OUTDIM * KDIM / 8];   // bf16 [256][32768] lo

// ============================================================================
// Helpers
// ============================================================================
__device__ __forceinline__ uint32_t smem_to_u32(const void* p) {
    uint32_t a;
    asm("{ .reg .u64 t; cvta.to.shared.u64 t, %1; cvt.u32.u64 %0, t; }"
        : "=r"(a) : "l"(p));
    return a;
}

__device__ __forceinline__ void cp_async16(uint32_t dst, const void* src) {
    asm volatile("cp.async.cg.shared.global [%0], [%1], 16;"
                 :: "r"(dst), "l"(src) : "memory");
}

__device__ __forceinline__ void mma16816(float acc[4],
                                         uint32_t a0, uint32_t a1,
                                         uint32_t a2, uint32_t a3,
                                         uint32_t b0, uint32_t b1) {
    asm volatile(
        "mma.sync.aligned.m16n8k16.row.col.f32.bf16.bf16.f32 "
        "{%0,%1,%2,%3}, {%4,%5,%6,%7}, {%8,%9}, {%0,%1,%2,%3};"
        : "+f"(acc[0]), "+f"(acc[1]), "+f"(acc[2]), "+f"(acc[3])
        : "r"(a0), "r"(a1), "r"(a2), "r"(a3), "r"(b0), "r"(b1));
}

// ============================================================================
// Kernel 1: prep — fouriercoeffs[2,O,I,G] f32 -> K-major bf16 hi/lo scratch
// ============================================================================
__global__ void prep_kernel(const float* __restrict__ cf) {
    size_t idx = (size_t)blockIdx.x * 256 + threadIdx.x;
    if (idx >= (size_t)OUTDIM * KDIM) return;
    int o = (int)(idx >> 15);            // KDIM = 2^15
    int k = (int)(idx & (KDIM - 1));
    int cs = k >> 14;
    int i  = (k >> 6) & (INPUTDIM - 1);
    int g  = k & (GRIDSZ - 1);
    float v = cf[(((size_t)cs * OUTDIM + o) * INPUTDIM + i) * GRIDSZ + g];
    __nv_bfloat16 h = __float2bfloat16(v);
    float hf = __bfloat162float(h);
    __nv_bfloat16 l = __float2bfloat16(v - hf);
    ((__nv_bfloat16*)g_Bhi)[idx] = h;
    ((__nv_bfloat16*)g_Blo)[idx] = l;
}

// ============================================================================
// Kernel 2: fused feature-gen + split-bf16 mma.sync GEMM
//   grid = 128 CTAs (32 M-tiles x 4 N-tiles), 256 threads
//   D[4096,256] = A[4096,32768] B^T + bias, 3 products (AhBh + AhBl + AlBh)
// ============================================================================
__global__ void __launch_bounds__(256, 1)
fourier_gemm(const float* __restrict__ x, const float* __restrict__ bias,
             float* __restrict__ out) {
    extern __shared__ char smem[];
    const uint32_t su32 = smem_to_u32(smem);
    const int tid = threadIdx.x;
    const int lid = tid & 31, wid = tid >> 5;
    const int wm = wid & 3, wn = wid >> 2;          // warp grid 4(M) x 2(N)
    const int mtile = blockIdx.x & (MTILES - 1);
    const int ntile = blockIdx.x >> 5;

    float acc[2][4][4];
    #pragma unroll
    for (int mt = 0; mt < 2; ++mt)
        #pragma unroll
        for (int nt = 0; nt < 4; ++nt)
            #pragma unroll
            for (int q = 0; q < 4; ++q) acc[mt][nt][q] = 0.f;

    // --- feature-gen thread mapping: row fb, g-half g0 ---
    const int fb = tid >> 1;                 // 0..127
    const int g0 = (tid & 1) * 32;
    const float* xrow = x + (size_t)(mtile * MTILE + fb) * INPUTDIM;

    // --- fragment-load lane constants ---
    const int rA = lid >> 2;                 // 0..7
    const int kc = (lid & 3) * 2;            // 0,2,4,6

    const char* bhp = (const char*)g_Bhi;
    const char* blp = (const char*)g_Blo;

    // ---------------- prologue: B[0] + A[0] into stage 0 ----------------
    {
        const int c = 0;
        #pragma unroll
        for (int q = 0; q < 4; ++q) {
            int idx = tid + q * 256;                  // 0..1023 segs of 16B
            int mat = idx >> 9;
            int r   = (idx >> 3) & 63;
            int seg = idx & 7;
            uint32_t dst = su32 + (mat ? OFF_BLO : OFF_BHI) + r * ROWB + seg * 16;
            const char* src = (mat ? blp : bhp)
                + (size_t)(ntile * NTILE + r) * (KDIM * 2) + (size_t)c * 128 + seg * 16;
            cp_async16(dst, src);
        }
        asm volatile("cp.async.commit_group;" ::: "memory");
    }
    {
        float xv = __ldg(xrow + 0);
        float S, C;   sincosf(xv, &S, &C);
        float s0, c0; sincosf(xv * (float)(g0 + 1), &s0, &c0);
        char* ph = smem + OFF_AHI + fb * ROWB;
        char* pl = smem + OFF_ALO + fb * ROWB;
        uint32_t prev_h = 0, prev_l = 0;
        #pragma unroll
        for (int j = 0; j < 32; ++j) {
            float v = c0;                            // chunk 0 => cs = 0 (cos)
            __nv_bfloat16 hb = __float2bfloat16(v);
            float hf = __bfloat162float(hb);
            __nv_bfloat16 lb = __float2bfloat16(v - hf);
            uint32_t hu = (uint32_t)__bfloat16_as_ushort(hb);
            uint32_t lu = (uint32_t)__bfloat16_as_ushort(lb);
            float cn = c0 * C - s0 * S;
            float sn = s0 * C + c0 * S;
            c0 = cn; s0 = sn;
            if (j & 1) {
                *(uint32_t*)(ph + (g0 + j - 1) * 2) = prev_h | (hu << 16);
                *(uint32_t*)(pl + (g0 + j - 1) * 2) = prev_l | (lu << 16);
            } else { prev_h = hu; prev_l = lu; }
        }
    }

    // ---------------- main loop ----------------
    int scur = 0;
    for (int it = 0; it < NCHUNK; ++it) {
        int snxt = (scur == NSTAGE - 1) ? 0 : scur + 1;

        if (it + 1 < NCHUNK) {
            const int c = it + 1;
            // B tile (hi+lo, 16 KB) via cp.async
            #pragma unroll
            for (int q = 0; q < 4; ++q) {
                int idx = tid + q * 256;
                int mat = idx >> 9;
                int r   = (idx >> 3) & 63;
                int seg = idx & 7;
                uint32_t dst = su32 + snxt * STAGE_BYTES
                             + (mat ? OFF_BLO : OFF_BHI) + r * ROWB + seg * 16;
                const char* src = (mat ? blp : bhp)
                    + (size_t)(ntile * NTILE + r) * (KDIM * 2) + (size_t)c * 128 + seg * 16;
                cp_async16(dst, src);
            }
            // A features via rotation recurrence, split hi/lo
            int cs = c >> 8, ii = c & (INPUTDIM - 1);
            float xv = __ldg(xrow + ii);
            float S, C;   sincosf(xv, &S, &C);
            float s0, c0; sincosf(xv * (float)(g0 + 1), &s0, &c0);
            char* ph = smem + snxt * STAGE_BYTES + OFF_AHI + fb * ROWB;
            char* pl = smem + snxt * STAGE_BYTES + OFF_ALO + fb * ROWB;
            uint32_t prev_h = 0, prev_l = 0;
            #pragma unroll
            for (int j = 0; j < 32; ++j) {
                float v = cs ? s0 : c0;
                __nv_bfloat16 hb = __float2bfloat16(v);
                float hf = __bfloat162float(hb);
                __nv_bfloat16 lb = __float2bfloat16(v - hf);
                uint32_t hu = (uint32_t)__bfloat16_as_ushort(hb);
                uint32_t lu = (uint32_t)__bfloat16_as_ushort(lb);
                float cn = c0 * C - s0 * S;
                float sn = s0 * C + c0 * S;
                c0 = cn; s0 = sn;
                if (j & 1) {
                    *(uint32_t*)(ph + (g0 + j - 1) * 2) = prev_h | (hu << 16);
                    *(uint32_t*)(pl + (g0 + j - 1) * 2) = prev_l | (lu << 16);
                } else { prev_h = hu; prev_l = lu; }
            }
        }
        asm volatile("cp.async.commit_group;" ::: "memory");
        asm volatile("cp.async.wait_group 1;" ::: "memory");
        __syncthreads();

        // ---- MMA over stage scur ----
        const char* pAh = smem + scur * STAGE_BYTES + OFF_AHI;
        const char* pAl = smem + scur * STAGE_BYTES + OFF_ALO;
        const char* pBh = smem + scur * STAGE_BYTES + OFF_BHI;
        const char* pBl = smem + scur * STAGE_BYTES + OFF_BLO;

        #pragma unroll
        for (int ks = 0; ks < 4; ++ks) {
            const int kb = ks * 16 + kc;             // k column for this lane
            uint32_t Ah[2][4], Al[2][4], Bh[4][2], Bl[4][2];

            #pragma unroll
            for (int mt = 0; mt < 2; ++mt) {
                const char* p = pAh + (wm * 32 + mt * 16 + rA) * ROWB + kb * 2;
                Ah[mt][0] = *(const uint32_t*)p;
                Ah[mt][1] = *(const uint32_t*)(p + 8 * ROWB);
                Ah[mt][2] = *(const uint32_t*)(p + 16);
                Ah[mt][3] = *(const uint32_t*)(p + 8 * ROWB + 16);
            }
            #pragma unroll
            for (int nt = 0; nt < 4; ++nt) {
                const char* p = pBh + (wn * 32 + nt * 8 + rA) * ROWB + kb * 2;
                Bh[nt][0] = *(const uint32_t*)p;
                Bh[nt][1] = *(const uint32_t*)(p + 16);
            }
            #pragma unroll
            for (int mt = 0; mt < 2; ++mt)
                #pragma unroll
                for (int nt = 0; nt < 4; ++nt)
                    mma16816(acc[mt][nt], Ah[mt][0], Ah[mt][1], Ah[mt][2], Ah[mt][3],
                             Bh[nt][0], Bh[nt][1]);

            #pragma unroll
            for (int nt = 0; nt < 4; ++nt) {
                const char* p = pBl + (wn * 32 + nt * 8 + rA) * ROWB + kb * 2;
                Bl[nt][0] = *(const uint32_t*)p;
                Bl[nt][1] = *(const uint32_t*)(p + 16);
            }
            #pragma unroll
            for (int mt = 0; mt < 2; ++mt)
                #pragma unroll
                for (int nt = 0; nt < 4; ++nt)
                    mma16816(acc[mt][nt], Ah[mt][0], Ah[mt][1], Ah[mt][2], Ah[mt][3],
                             Bl[nt][0], Bl[nt][1]);

            #pragma unroll
            for (int mt = 0; mt < 2; ++mt) {
                const char* p = pAl + (wm * 32 + mt * 16 + rA) * ROWB + kb * 2;
                Al[mt][0] = *(const uint32_t*)p;
                Al[mt][1] = *(const uint32_t*)(p + 8 * ROWB);
                Al[mt][2] = *(const uint32_t*)(p + 16);
                Al[mt][3] = *(const uint32_t*)(p + 8 * ROWB + 16);
            }
            #pragma unroll
            for (int mt = 0; mt < 2; ++mt)
                #pragma unroll
                for (int nt = 0; nt < 4; ++nt)
                    mma16816(acc[mt][nt], Al[mt][0], Al[mt][1], Al[mt][2], Al[mt][3],
                             Bh[nt][0], Bh[nt][1]);
        }
        scur = snxt;
    }

    // ---------------- epilogue: acc + bias -> out ----------------
    #pragma unroll
    for (int mt = 0; mt < 2; ++mt) {
        int r0 = mtile * MTILE + wm * 32 + mt * 16 + (lid >> 2);
        #pragma unroll
        for (int nt = 0; nt < 4; ++nt) {
            int c0 = ntile * NTILE + wn * 32 + nt * 8 + (lid & 3) * 2;
            float b0 = __ldg(bias + c0);
            float b1 = __ldg(bias + c0 + 1);
            *(float2*)(out + (size_t)r0 * OUTDIM + c0) =
                make_float2(acc[mt][nt][0] + b0, acc[mt][nt][1] + b1);
            *(float2*)(out + (size_t)(r0 + 8) * OUTDIM + c0) =
                make_float2(acc[mt][nt][2] + b0, acc[mt][nt][3] + b1);
        }
    }
}

// ============================================================================
// Launch
// ============================================================================
extern "C" void kernel_launch(void* const* d_in, const int* in_sizes, int n_in,
                              void* d_out, int out_size) {
    const float* x    = (const float*)d_in[0];
    const float* cf   = (const float*)d_in[1];
    const float* bias = (const float*)d_in[2];
    float* out = (float*)d_out;

    cudaFuncSetAttribute(fourier_gemm,
                         cudaFuncAttributeMaxDynamicSharedMemorySize, SMEM_BYTES);

    prep_kernel<<<(OUTDIM * KDIM + 255) / 256, 256>>>(cf);
    fourier_gemm<<<MTILES * NTILES, 256, SMEM_BYTES>>>(x, bias, out);
    (void)in_sizes; (void)n_in; (void)out_size;
}

// round 4
// speedup vs baseline: 1.0174x; 1.0174x over previous
#include <cuda_runtime.h>
#include <cuda_bf16.h>
#include <cstdint>

// ============================================================================
// Problem constants
// ============================================================================
#define BATCH    4096
#define INPUTDIM 256
#define OUTDIM   256
#define GRIDSZ   64
#define KDIM     32768          // k = cs*16384 + i*64 + g
#define NCHUNK   512            // K chunks of 64 (one (cs,i) pair each)
#define MTILE    128
#define NTILE    64
#define MTILES   (BATCH / MTILE)   // 32
#define NTILES   (OUTDIM / NTILE)  // 4
#define NTHREADS 512

// SMEM stage layout: padded rows of 72 bf16 = 144 B (conflict-free LDSM)
#define ROWB        144
#define A_BYTES     (128 * ROWB)            // 18432
#define B_BYTES     (64 * ROWB)             // 9216
#define OFF_AHI     0
#define OFF_ALO     (A_BYTES)
#define OFF_BHI     (2 * A_BYTES)
#define OFF_BLO     (2 * A_BYTES + B_BYTES)
#define STAGE_BYTES (2 * A_BYTES + 2 * B_BYTES)   // 55296
#define NSTAGE      3
#define SMEM_BYTES  (NSTAGE * STAGE_BYTES)        // 165888

// ============================================================================
// Scratch (device globals — no allocation allowed)
// ============================================================================
__device__ uint4 g_Bhi[(size_t)OUTDIM * KDIM / 8];   // bf16 [256][32768] hi
__device__ uint4 g_Blo[(size_t)OUTDIM * KDIM / 8];   // bf16 [256][32768] lo

// ============================================================================
// Helpers
// ============================================================================
__device__ __forceinline__ uint32_t smem_to_u32(const void* p) {
    uint32_t a;
    asm("{ .reg .u64 t; cvta.to.shared.u64 t, %1; cvt.u32.u64 %0, t; }"
        : "=r"(a) : "l"(p));
    return a;
}

__device__ __forceinline__ void cp_async16(uint32_t dst, const void* src) {
    asm volatile("cp.async.cg.shared.global [%0], [%1], 16;"
                 :: "r"(dst), "l"(src) : "memory");
}

__device__ __forceinline__ void ldsm_x4(uint32_t r[4], uint32_t addr) {
    asm volatile("ldmatrix.sync.aligned.m8n8.x4.shared.b16 {%0,%1,%2,%3}, [%4];"
                 : "=r"(r[0]), "=r"(r[1]), "=r"(r[2]), "=r"(r[3]) : "r"(addr));
}

__device__ __forceinline__ void mma16816(float acc[4],
                                         const uint32_t a[4],
                                         uint32_t b0, uint32_t b1) {
    asm volatile(
        "mma.sync.aligned.m16n8k16.row.col.f32.bf16.bf16.f32 "
        "{%0,%1,%2,%3}, {%4,%5,%6,%7}, {%8,%9}, {%0,%1,%2,%3};"
        : "+f"(acc[0]), "+f"(acc[1]), "+f"(acc[2]), "+f"(acc[3])
        : "r"(a[0]), "r"(a[1]), "r"(a[2]), "r"(a[3]), "r"(b0), "r"(b1));
}

// ============================================================================
// Kernel 1: prep — fouriercoeffs[2,O,I,G] f32 -> K-major bf16 hi/lo scratch
// ============================================================================
__global__ void prep_kernel(const float* __restrict__ cf) {
    size_t idx = (size_t)blockIdx.x * 256 + threadIdx.x;
    if (idx >= (size_t)OUTDIM * KDIM) return;
    int o = (int)(idx >> 15);            // KDIM = 2^15
    int k = (int)(idx & (KDIM - 1));
    int cs = k >> 14;
    int i  = (k >> 6) & (INPUTDIM - 1);
    int g  = k & (GRIDSZ - 1);
    float v = cf[(((size_t)cs * OUTDIM + o) * INPUTDIM + i) * GRIDSZ + g];
    __nv_bfloat16 h = __float2bfloat16(v);
    float hf = __bfloat162float(h);
    __nv_bfloat16 l = __float2bfloat16(v - hf);
    ((__nv_bfloat16*)g_Bhi)[idx] = h;
    ((__nv_bfloat16*)g_Blo)[idx] = l;
}

// ============================================================================
// Kernel 2: fused feature-gen + split-bf16 mma.sync GEMM
//   grid = 128 CTAs (32 M x 4 N), 512 threads (16 warps, 4Mx4N, 32x16 tiles)
//   Loop order: wait -> barrier -> MMA(s) -> prefetch+gen(s+2) -> commit
// ============================================================================
__global__ void __launch_bounds__(NTHREADS, 1)
fourier_gemm(const float* __restrict__ x, const float* __restrict__ bias,
             float* __restrict__ out) {
    extern __shared__ char smem[];
    const uint32_t su32 = smem_to_u32(smem);
    const int tid = threadIdx.x;
    const int lid = tid & 31, wid = tid >> 5;
    const int wm = wid & 3, wn = wid >> 2;          // warp grid 4(M) x 4(N)
    const int mtile = blockIdx.x & (MTILES - 1);
    const int ntile = blockIdx.x >> 5;

    float acc[2][2][4];
    #pragma unroll
    for (int mt = 0; mt < 2; ++mt)
        #pragma unroll
        for (int nt = 0; nt < 2; ++nt)
            #pragma unroll
            for (int q = 0; q < 4; ++q) acc[mt][nt][q] = 0.f;

    // --- feature-gen mapping: 4 threads per row ---
    const int fb = tid >> 2;                 // 0..127
    const int g0 = (tid & 3) * 16;           // 16 g-values per thread
    const float* xrow = x + (size_t)(mtile * MTILE + fb) * INPUTDIM;

    // --- ldmatrix lane offsets ---
    const int mat = lid >> 3, mr = lid & 7;
    const uint32_t a_off =
        (uint32_t)((wm * 32 + (mat & 1) * 8 + mr) * ROWB + ((mat >> 1) * 8) * 2);
    const uint32_t b_off =
        (uint32_t)((wn * 16 + (mat >> 1) * 8 + mr) * ROWB + ((mat & 1) * 8) * 2);

    const char* bhp = (const char*)g_Bhi;
    const char* blp = (const char*)g_Blo;

    // ---------- helpers as lambdas ----------
    auto prefetchB = [&](int c, int stg) {
        #pragma unroll
        for (int q = 0; q < 2; ++q) {
            int idx = tid + q * NTHREADS;            // 0..1023 segs of 16B
            int isLo = idx >> 9;
            int r   = (idx >> 3) & 63;
            int seg = idx & 7;
            uint32_t dst = su32 + stg * STAGE_BYTES
                         + (isLo ? OFF_BLO : OFF_BHI) + r * ROWB + seg * 16;
            const char* src = (isLo ? blp : bhp)
                + (size_t)(ntile * NTILE + r) * (KDIM * 2) + (size_t)c * 128 + seg * 16;
            cp_async16(dst, src);
        }
    };
    auto genA = [&](int c, int stg) {
        int cs = c >> 8, ii = c & (INPUTDIM - 1);
        float xv = __ldg(xrow + ii);
        float S, C;   sincosf(xv, &S, &C);
        float s0, c0; sincosf(xv * (float)(g0 + 1), &s0, &c0);
        char* ph = smem + stg * STAGE_BYTES + OFF_AHI + fb * ROWB + g0 * 2;
        char* pl = smem + stg * STAGE_BYTES + OFF_ALO + fb * ROWB + g0 * 2;
        uint32_t prev_h = 0, prev_l = 0;
        #pragma unroll
        for (int j = 0; j < 16; ++j) {
            float v = cs ? s0 : c0;
            __nv_bfloat16 hb = __float2bfloat16(v);
            float hf = __bfloat162float(hb);
            __nv_bfloat16 lb = __float2bfloat16(v - hf);
            uint32_t hu = (uint32_t)__bfloat16_as_ushort(hb);
            uint32_t lu = (uint32_t)__bfloat16_as_ushort(lb);
            float cn = c0 * C - s0 * S;
            float sn = s0 * C + c0 * S;
            c0 = cn; s0 = sn;
            if (j & 1) {
                *(uint32_t*)(ph + (j - 1) * 2) = prev_h | (hu << 16);
                *(uint32_t*)(pl + (j - 1) * 2) = prev_l | (lu << 16);
            } else { prev_h = hu; prev_l = lu; }
        }
    };

    // ---------------- prologue: stages 0,1 ----------------
    prefetchB(0, 0);
    asm volatile("cp.async.commit_group;" ::: "memory");
    prefetchB(1, 1);
    asm volatile("cp.async.commit_group;" ::: "memory");
    genA(0, 0);
    genA(1, 1);

    // ---------------- main loop ----------------
    int scur = 0;
    for (int it = 0; it < NCHUNK; ++it) {
        asm volatile("cp.async.wait_group 1;" ::: "memory");
        __syncthreads();

        // ---- MMA over stage scur ----
        const uint32_t sbase = su32 + scur * STAGE_BYTES;
        const uint32_t aHi = sbase + OFF_AHI + a_off;
        const uint32_t aLo = sbase + OFF_ALO + a_off;
        const uint32_t bHi = sbase + OFF_BHI + b_off;
        const uint32_t bLo = sbase + OFF_BLO + b_off;

        #pragma unroll
        for (int ks = 0; ks < 4; ++ks) {
            const uint32_t ko = ks * 32;
            uint32_t Ah[2][4], Al[2][4], Bh[4], Bl[4];
            ldsm_x4(Ah[0], aHi + ko);
            ldsm_x4(Ah[1], aHi + 16 * ROWB + ko);
            ldsm_x4(Bh, bHi + ko);                       // Bh = {n0k0,n0k8,n1k0,n1k8}
            #pragma unroll
            for (int mt = 0; mt < 2; ++mt)
                #pragma unroll
                for (int nt = 0; nt < 2; ++nt)
                    mma16816(acc[mt][nt], Ah[mt], Bh[2 * nt], Bh[2 * nt + 1]);
            ldsm_x4(Bl, bLo + ko);
            #pragma unroll
            for (int mt = 0; mt < 2; ++mt)
                #pragma unroll
                for (int nt = 0; nt < 2; ++nt)
                    mma16816(acc[mt][nt], Ah[mt], Bl[2 * nt], Bl[2 * nt + 1]);
            ldsm_x4(Al[0], aLo + ko);
            ldsm_x4(Al[1], aLo + 16 * ROWB + ko);
            #pragma unroll
            for (int mt = 0; mt < 2; ++mt)
                #pragma unroll
                for (int nt = 0; nt < 2; ++nt)
                    mma16816(acc[mt][nt], Al[mt], Bh[2 * nt], Bh[2 * nt + 1]);
        }

        // ---- prefetch + generate stage it+2 (overlaps other warps' MMA) ----
        int snxt2 = scur + 2; if (snxt2 >= NSTAGE) snxt2 -= NSTAGE;
        if (it + 2 < NCHUNK) prefetchB(it + 2, snxt2);
        asm volatile("cp.async.commit_group;" ::: "memory");
        if (it + 2 < NCHUNK) genA(it + 2, snxt2);

        scur = (scur == NSTAGE - 1) ? 0 : scur + 1;
    }

    // ---------------- epilogue: acc + bias -> out ----------------
    #pragma unroll
    for (int mt = 0; mt < 2; ++mt) {
        int r0 = mtile * MTILE + wm * 32 + mt * 16 + (lid >> 2);
        #pragma unroll
        for (int nt = 0; nt < 2; ++nt) {
            int c0 = ntile * NTILE + wn * 16 + nt * 8 + (lid & 3) * 2;
            float b0 = __ldg(bias + c0);
            float b1 = __ldg(bias + c0 + 1);
            *(float2*)(out + (size_t)r0 * OUTDIM + c0) =
                make_float2(acc[mt][nt][0] + b0, acc[mt][nt][1] + b1);
            *(float2*)(out + (size_t)(r0 + 8) * OUTDIM + c0) =
                make_float2(acc[mt][nt][2] + b0, acc[mt][nt][3] + b1);
        }
    }
}

// ============================================================================
// Launch
// ============================================================================
extern "C" void kernel_launch(void* const* d_in, const int* in_sizes, int n_in,
                              void* d_out, int out_size) {
    const float* x    = (const float*)d_in[0];
    const float* cf   = (const float*)d_in[1];
    const float* bias = (const float*)d_in[2];
    float* out = (float*)d_out;

    cudaFuncSetAttribute(fourier_gemm,
                         cudaFuncAttributeMaxDynamicSharedMemorySize, SMEM_BYTES);

    prep_kernel<<<(OUTDIM * KDIM + 255) / 256, 256>>>(cf);
    fourier_gemm<<<MTILES * NTILES, NTHREADS, SMEM_BYTES>>>(x, bias, out);
    (void)in_sizes; (void)n_in; (void)out_size;
}

// round 5
// speedup vs baseline: 1.5278x; 1.5016x over previous
#include <cuda_runtime.h>
#include <cuda_bf16.h>
#include <cstdint>

// ============================================================================
// Problem constants
// ============================================================================
#define BATCH    4096
#define INPUTDIM 256
#define OUTDIM   256
#define GRIDSZ   64
#define KDIM     32768            // k = cs*16384 + i*64 + g
#define NPAIR    256              // loop over i; each pair = chunks (i, i+16384/64)
#define MTILE    128
#define NTILE    64
#define MTILES   (BATCH / MTILE)  // 32
#define NTILES   (OUTDIM / NTILE) // 4
#define NTHREADS 512
#define NCONS    256              // consumer threads (warps 0-7)

// SMEM stage: 4 A buffers (cosHi,cosLo,sinHi,sinLo) + 4 B buffers
#define ROWB     144
#define ABUF     (128 * ROWB)     // 18432
#define BBUF     (64 * ROWB)      // 9216
#define OFF_ACHI 0
#define OFF_ACLO (ABUF)
#define OFF_ASHI (2 * ABUF)
#define OFF_ASLO (3 * ABUF)
#define OFF_B0   (4 * ABUF)       // 4 contiguous B buffers: cHi,cLo,sHi,sLo
#define STAGEB   (4 * ABUF + 4 * BBUF)   // 110592
#define NSTAGE   2
#define SM_BAR   (NSTAGE * STAGEB)       // 4 mbarriers: full0,full1,empty0,empty1
#define SMEM_BYTES (NSTAGE * STAGEB + 64)

// ============================================================================
// Scratch (device globals — no allocation allowed)
// ============================================================================
__device__ uint4 g_Bhi[(size_t)OUTDIM * KDIM / 8];   // bf16 [256][32768] hi
__device__ uint4 g_Blo[(size_t)OUTDIM * KDIM / 8];   // bf16 [256][32768] lo

// ============================================================================
// Helpers
// ============================================================================
__device__ __forceinline__ uint32_t smem_to_u32(const void* p) {
    uint32_t a;
    asm("{ .reg .u64 t; cvta.to.shared.u64 t, %1; cvt.u32.u64 %0, t; }"
        : "=r"(a) : "l"(p));
    return a;
}

__device__ __forceinline__ void cp_async16(uint32_t dst, const void* src) {
    asm volatile("cp.async.cg.shared.global [%0], [%1], 16;"
                 :: "r"(dst), "l"(src) : "memory");
}

__device__ __forceinline__ void ldsm_x4(uint32_t r[4], uint32_t addr) {
    asm volatile("ldmatrix.sync.aligned.m8n8.x4.shared.b16 {%0,%1,%2,%3}, [%4];"
                 : "=r"(r[0]), "=r"(r[1]), "=r"(r[2]), "=r"(r[3]) : "r"(addr));
}

__device__ __forceinline__ void mma16816(float acc[4],
                                         const uint32_t a[4],
                                         uint32_t b0, uint32_t b1) {
    asm volatile(
        "mma.sync.aligned.m16n8k16.row.col.f32.bf16.bf16.f32 "
        "{%0,%1,%2,%3}, {%4,%5,%6,%7}, {%8,%9}, {%0,%1,%2,%3};"
        : "+f"(acc[0]), "+f"(acc[1]), "+f"(acc[2]), "+f"(acc[3])
        : "r"(a[0]), "r"(a[1]), "r"(a[2]), "r"(a[3]), "r"(b0), "r"(b1));
}

#define MBAR_INIT(addr, cnt) \
    asm volatile("mbarrier.init.shared.b64 [%0], %1;" \
                 :: "r"((uint32_t)(addr)), "r"((uint32_t)(cnt)) : "memory")

#define MBAR_ARRIVE(addr) \
    asm volatile("mbarrier.arrive.shared.b64 _, [%0];" \
                 :: "r"((uint32_t)(addr)) : "memory")

#define MBAR_WAIT(addr, parity) do { \
    uint32_t _m = (uint32_t)(addr), _p = (uint32_t)(parity), _d; \
    asm volatile( \
        "{\n\t.reg .pred p;\n\t" \
        "mbarrier.try_wait.parity.acquire.cta.shared::cta.b64 p, [%1], %2;\n\t" \
        "selp.b32 %0, 1, 0, p;\n\t}" \
        : "=r"(_d) : "r"(_m), "r"(_p) : "memory"); \
    if (!_d) { \
        asm volatile( \
            "{\n\t.reg .pred P1;\n\t" \
            "WL_%=:\n\t" \
            "mbarrier.try_wait.parity.acquire.cta.shared::cta.b64 P1, [%0], %1, 0x989680;\n\t" \
            "@P1 bra.uni WD_%=;\n\t" \
            "bra.uni WL_%=;\n\t" \
            "WD_%=:\n\t}" \
            :: "r"(_m), "r"(_p) : "memory"); \
    } \
} while (0)

// ============================================================================
// Kernel 1: prep — fouriercoeffs[2,O,I,G] f32 -> K-major bf16 hi/lo scratch
// ============================================================================
__global__ void prep_kernel(const float* __restrict__ cf) {
    size_t idx = (size_t)blockIdx.x * 256 + threadIdx.x;
    if (idx >= (size_t)OUTDIM * KDIM) return;
    int o = (int)(idx >> 15);            // KDIM = 2^15
    int k = (int)(idx & (KDIM - 1));
    int cs = k >> 14;
    int i  = (k >> 6) & (INPUTDIM - 1);
    int g  = k & (GRIDSZ - 1);
    float v = cf[(((size_t)cs * OUTDIM + o) * INPUTDIM + i) * GRIDSZ + g];
    __nv_bfloat16 h = __float2bfloat16(v);
    float hf = __bfloat162float(h);
    __nv_bfloat16 l = __float2bfloat16(v - hf);
    ((__nv_bfloat16*)g_Bhi)[idx] = h;
    ((__nv_bfloat16*)g_Blo)[idx] = l;
}

// ============================================================================
// Kernel 2: warp-specialized fused GEMM
//   128 CTAs (32 M x 4 N), 512 threads:
//     warps 0-7  : consumers — LDSM + HMMA only (4M x 2N, 32x32 warp tiles)
//     warps 8-15 : producers — feature-gen (cos+sin per rotation) + B cp.async
//   Pipeline over i (chunk PAIRS): 2 stages, mbarrier full/empty ring.
// ============================================================================
__global__ void __launch_bounds__(NTHREADS, 1)
fourier_gemm(const float* __restrict__ x, const float* __restrict__ bias,
             float* __restrict__ out) {
    extern __shared__ char smem[];
    const uint32_t su32 = smem_to_u32(smem);
    const int tid = threadIdx.x;
    const int lid = tid & 31, wid = tid >> 5;
    const int mtile = blockIdx.x & (MTILES - 1);
    const int ntile = blockIdx.x >> 5;

    const uint32_t bar_full0  = su32 + SM_BAR;
    const uint32_t bar_full1  = su32 + SM_BAR + 8;
    const uint32_t bar_empty0 = su32 + SM_BAR + 16;
    const uint32_t bar_empty1 = su32 + SM_BAR + 24;

    if (tid == 0) {
        MBAR_INIT(bar_full0,  NTHREADS - NCONS);   // producer arrivals
        MBAR_INIT(bar_full1,  NTHREADS - NCONS);
        MBAR_INIT(bar_empty0, NCONS);              // consumer arrivals
        MBAR_INIT(bar_empty1, NCONS);
    }
    __syncthreads();

    if (tid < NCONS) {
        // ==================== CONSUMER ====================
        const int wm = wid & 3, wn = wid >> 2;     // 4(M) x 2(N)
        const int mat = lid >> 3, mr = lid & 7;
        const uint32_t a_off =
            (uint32_t)((wm * 32 + (mat & 1) * 8 + mr) * ROWB + ((mat >> 1) * 8) * 2);
        const uint32_t b_off =
            (uint32_t)((wn * 32 + (mat >> 1) * 8 + mr) * ROWB + ((mat & 1) * 8) * 2);

        float acc[2][4][4];
        #pragma unroll
        for (int mt = 0; mt < 2; ++mt)
            #pragma unroll
            for (int nt = 0; nt < 4; ++nt)
                #pragma unroll
                for (int q = 0; q < 4; ++q) acc[mt][nt][q] = 0.f;

        int phf0 = 0, phf1 = 0;
        for (int it = 0; it < NPAIR; ++it) {
            const int s = it & 1;
            if (s == 0) { MBAR_WAIT(bar_full0, phf0); phf0 ^= 1; }
            else        { MBAR_WAIT(bar_full1, phf1); phf1 ^= 1; }

            const uint32_t sbase = su32 + s * STAGEB;
            #pragma unroll
            for (int q = 0; q < 2; ++q) {          // q=0 cos-chunk, q=1 sin-chunk
                const uint32_t aHi = sbase + (q ? OFF_ASHI : OFF_ACHI) + a_off;
                const uint32_t aLo = sbase + (q ? OFF_ASLO : OFF_ACLO) + a_off;
                const uint32_t bHi = sbase + OFF_B0 + (q ? 2 * BBUF : 0) + b_off;
                const uint32_t bLo = bHi + BBUF;

                #pragma unroll
                for (int ks = 0; ks < 4; ++ks) {
                    const uint32_t ko = ks * 32;
                    uint32_t Ah[2][4], Al[2][4], Bh[2][4], Bl[2][4];
                    ldsm_x4(Ah[0], aHi + ko);
                    ldsm_x4(Ah[1], aHi + 16 * ROWB + ko);
                    ldsm_x4(Bh[0], bHi + ko);
                    ldsm_x4(Bh[1], bHi + 16 * ROWB + ko);
                    #pragma unroll
                    for (int mt = 0; mt < 2; ++mt)
                        #pragma unroll
                        for (int nt = 0; nt < 2; ++nt) {
                            mma16816(acc[mt][nt * 2],     Ah[mt], Bh[nt][0], Bh[nt][1]);
                            mma16816(acc[mt][nt * 2 + 1], Ah[mt], Bh[nt][2], Bh[nt][3]);
                        }
                    ldsm_x4(Bl[0], bLo + ko);
                    ldsm_x4(Bl[1], bLo + 16 * ROWB + ko);
                    #pragma unroll
                    for (int mt = 0; mt < 2; ++mt)
                        #pragma unroll
                        for (int nt = 0; nt < 2; ++nt) {
                            mma16816(acc[mt][nt * 2],     Ah[mt], Bl[nt][0], Bl[nt][1]);
                            mma16816(acc[mt][nt * 2 + 1], Ah[mt], Bl[nt][2], Bl[nt][3]);
                        }
                    ldsm_x4(Al[0], aLo + ko);
                    ldsm_x4(Al[1], aLo + 16 * ROWB + ko);
                    #pragma unroll
                    for (int mt = 0; mt < 2; ++mt)
                        #pragma unroll
                        for (int nt = 0; nt < 2; ++nt) {
                            mma16816(acc[mt][nt * 2],     Al[mt], Bh[nt][0], Bh[nt][1]);
                            mma16816(acc[mt][nt * 2 + 1], Al[mt], Bh[nt][2], Bh[nt][3]);
                        }
                }
            }
            MBAR_ARRIVE(s ? bar_empty1 : bar_empty0);
        }

        // ---- epilogue ----
        #pragma unroll
        for (int mt = 0; mt < 2; ++mt) {
            int r0 = mtile * MTILE + wm * 32 + mt * 16 + (lid >> 2);
            #pragma unroll
            for (int nt = 0; nt < 4; ++nt) {
                int c0 = ntile * NTILE + wn * 32 + nt * 8 + (lid & 3) * 2;
                float b0 = __ldg(bias + c0);
                float b1 = __ldg(bias + c0 + 1);
                *(float2*)(out + (size_t)r0 * OUTDIM + c0) =
                    make_float2(acc[mt][nt][0] + b0, acc[mt][nt][1] + b1);
                *(float2*)(out + (size_t)(r0 + 8) * OUTDIM + c0) =
                    make_float2(acc[mt][nt][2] + b0, acc[mt][nt][3] + b1);
            }
        }
    } else {
        // ==================== PRODUCER ====================
        const int ptid = tid - NCONS;               // 0..255
        const int fb = ptid >> 1;                   // row 0..127
        const int g0 = (ptid & 1) * 32;             // 32 frequencies per thread
        const float* xrow = x + (size_t)(mtile * MTILE + fb) * INPUTDIM;
        const char* bhp = (const char*)g_Bhi;
        const char* blp = (const char*)g_Blo;

        int phe0 = 0, phe1 = 0;
        for (int it = 0; it < NPAIR; ++it) {
            const int s = it & 1;
            if (it >= NSTAGE) {
                if (s == 0) { MBAR_WAIT(bar_empty0, phe0); phe0 ^= 1; }
                else        { MBAR_WAIT(bar_empty1, phe1); phe1 ^= 1; }
            }
            const uint32_t sbase = su32 + s * STAGEB;

            // ---- B tiles: 4 buffers (cosHi,cosLo,sinHi,sinLo), 32 KB ----
            #pragma unroll
            for (int q = 0; q < 8; ++q) {
                int idx = ptid + q * 256;            // 0..2047 segs of 16B
                int buf = idx >> 9;                  // 0..3
                int r   = (idx >> 3) & 63;
                int seg = idx & 7;
                int c   = (buf >> 1) * (NPAIR) + it; // cs*256 + i
                uint32_t dst = sbase + OFF_B0 + buf * BBUF + r * ROWB + seg * 16;
                const char* src = ((buf & 1) ? blp : bhp)
                    + (size_t)(ntile * NTILE + r) * (KDIM * 2)
                    + (size_t)c * 128 + seg * 16;
                cp_async16(dst, src);
            }
            asm volatile("cp.async.commit_group;" ::: "memory");

            // ---- A features: one rotation pass fills cos AND sin tiles ----
            {
                float xv = __ldg(xrow + it);
                float S, C;   sincosf(xv, &S, &C);
                float s0, c0; sincosf(xv * (float)(g0 + 1), &s0, &c0);
                char* pch = smem + s * STAGEB + OFF_ACHI + fb * ROWB + g0 * 2;
                char* pcl = smem + s * STAGEB + OFF_ACLO + fb * ROWB + g0 * 2;
                char* psh = smem + s * STAGEB + OFF_ASHI + fb * ROWB + g0 * 2;
                char* psl = smem + s * STAGEB + OFF_ASLO + fb * ROWB + g0 * 2;
                uint32_t pc_h = 0, pc_l = 0, ps_h = 0, ps_l = 0;
                #pragma unroll
                for (int j = 0; j < 32; ++j) {
                    __nv_bfloat16 hcb = __float2bfloat16(c0);
                    __nv_bfloat16 lcb = __float2bfloat16(c0 - __bfloat162float(hcb));
                    __nv_bfloat16 hsb = __float2bfloat16(s0);
                    __nv_bfloat16 lsb = __float2bfloat16(s0 - __bfloat162float(hsb));
                    uint32_t hc = (uint32_t)__bfloat16_as_ushort(hcb);
                    uint32_t lc = (uint32_t)__bfloat16_as_ushort(lcb);
                    uint32_t hs = (uint32_t)__bfloat16_as_ushort(hsb);
                    uint32_t ls = (uint32_t)__bfloat16_as_ushort(lsb);
                    float cn = c0 * C - s0 * S;
                    float sn = s0 * C + c0 * S;
                    c0 = cn; s0 = sn;
                    if (j & 1) {
                        int off = (j - 1) * 2;
                        *(uint32_t*)(pch + off) = pc_h | (hc << 16);
                        *(uint32_t*)(pcl + off) = pc_l | (lc << 16);
                        *(uint32_t*)(psh + off) = ps_h | (hs << 16);
                        *(uint32_t*)(psl + off) = ps_l | (ls << 16);
                    } else { pc_h = hc; pc_l = lc; ps_h = hs; ps_l = ls; }
                }
            }

            asm volatile("cp.async.wait_group 0;" ::: "memory");
            MBAR_ARRIVE(s ? bar_full1 : bar_full0);
        }
    }
}

// ============================================================================
// Launch
// ============================================================================
extern "C" void kernel_launch(void* const* d_in, const int* in_sizes, int n_in,
                              void* d_out, int out_size) {
    const float* x    = (const float*)d_in[0];
    const float* cf   = (const float*)d_in[1];
    const float* bias = (const float*)d_in[2];
    float* out = (float*)d_out;

    cudaFuncSetAttribute(fourier_gemm,
                         cudaFuncAttributeMaxDynamicSharedMemorySize, SMEM_BYTES);

    prep_kernel<<<(OUTDIM * KDIM + 255) / 256, 256>>>(cf);
    fourier_gemm<<<MTILES * NTILES, NTHREADS, SMEM_BYTES>>>(x, bias, out);
    (void)in_sizes; (void)n_in; (void)out_size;
}

// round 6
// speedup vs baseline: 1.5735x; 1.0299x over previous
#include <cuda_runtime.h>
#include <cuda_bf16.h>
#include <cstdint>

// ============================================================================
// Problem constants
// ============================================================================
#define BATCH    4096
#define INPUTDIM 256
#define OUTDIM   256
#define GRIDSZ   64
#define KDIM     32768            // k = cs*16384 + i*64 + g
#define NPAIR    256              // loop over i; pair = (cos chunk i, sin chunk i)
#define MTILE    128
#define NTILE    64
#define MTILES   (BATCH / MTILE)  // 32
#define NTILES   (OUTDIM / NTILE) // 4
#define NTHREADS 384
#define NCONS    128              // consumer threads (warps 0-3)
#define NPROD    256              // producer threads (warps 4-11)

// SMEM stage: 4 A buffers (cosHi,cosLo,sinHi,sinLo) + 4 B buffers
#define ROWB     144
#define ABUF     (128 * ROWB)     // 18432
#define BBUF     (64 * ROWB)      // 9216
#define OFF_ACHI 0
#define OFF_ACLO (ABUF)
#define OFF_ASHI (2 * ABUF)
#define OFF_ASLO (3 * ABUF)
#define OFF_B0   (4 * ABUF)       // 4 contiguous B buffers: cHi,cLo,sHi,sLo
#define STAGEB   (4 * ABUF + 4 * BBUF)   // 110592
#define NSTAGE   2
#define SM_BAR   (NSTAGE * STAGEB)
#define SMEM_BYTES (NSTAGE * STAGEB + 64)

// ============================================================================
// Scratch (device globals — no allocation allowed)
// ============================================================================
__device__ uint4 g_Bhi[(size_t)OUTDIM * KDIM / 8];   // bf16 [256][32768] hi
__device__ uint4 g_Blo[(size_t)OUTDIM * KDIM / 8];   // bf16 [256][32768] lo

// ============================================================================
// Helpers
// ============================================================================
__device__ __forceinline__ uint32_t smem_to_u32(const void* p) {
    uint32_t a;
    asm("{ .reg .u64 t; cvta.to.shared.u64 t, %1; cvt.u32.u64 %0, t; }"
        : "=r"(a) : "l"(p));
    return a;
}

__device__ __forceinline__ void cp_async16(uint32_t dst, const void* src) {
    asm volatile("cp.async.cg.shared.global [%0], [%1], 16;"
                 :: "r"(dst), "l"(src) : "memory");
}

__device__ __forceinline__ void ldsm_x4(uint32_t r[4], uint32_t addr) {
    asm volatile("ldmatrix.sync.aligned.m8n8.x4.shared.b16 {%0,%1,%2,%3}, [%4];"
                 : "=r"(r[0]), "=r"(r[1]), "=r"(r[2]), "=r"(r[3]) : "r"(addr));
}

__device__ __forceinline__ void mma16816(float acc[4],
                                         const uint32_t a[4],
                                         uint32_t b0, uint32_t b1) {
    asm volatile(
        "mma.sync.aligned.m16n8k16.row.col.f32.bf16.bf16.f32 "
        "{%0,%1,%2,%3}, {%4,%5,%6,%7}, {%8,%9}, {%0,%1,%2,%3};"
        : "+f"(acc[0]), "+f"(acc[1]), "+f"(acc[2]), "+f"(acc[3])
        : "r"(a[0]), "r"(a[1]), "r"(a[2]), "r"(a[3]), "r"(b0), "r"(b1));
}

#define MBAR_INIT(addr, cnt) \
    asm volatile("mbarrier.init.shared.b64 [%0], %1;" \
                 :: "r"((uint32_t)(addr)), "r"((uint32_t)(cnt)) : "memory")

#define MBAR_ARRIVE(addr) \
    asm volatile("mbarrier.arrive.shared.b64 _, [%0];" \
                 :: "r"((uint32_t)(addr)) : "memory")

#define MBAR_WAIT(addr, parity) do { \
    uint32_t _m = (uint32_t)(addr), _p = (uint32_t)(parity), _d; \
    asm volatile( \
        "{\n\t.reg .pred p;\n\t" \
        "mbarrier.try_wait.parity.acquire.cta.shared::cta.b64 p, [%1], %2;\n\t" \
        "selp.b32 %0, 1, 0, p;\n\t}" \
        : "=r"(_d) : "r"(_m), "r"(_p) : "memory"); \
    if (!_d) { \
        asm volatile( \
            "{\n\t.reg .pred P1;\n\t" \
            "WL_%=:\n\t" \
            "mbarrier.try_wait.parity.acquire.cta.shared::cta.b64 P1, [%0], %1, 0x989680;\n\t" \
            "@P1 bra.uni WD_%=;\n\t" \
            "bra.uni WL_%=;\n\t" \
            "WD_%=:\n\t}" \
            :: "r"(_m), "r"(_p) : "memory"); \
    } \
} while (0)

// ============================================================================
// Kernel 1: prep — fouriercoeffs[2,O,I,G] f32 -> K-major bf16 hi/lo scratch
// ============================================================================
__global__ void prep_kernel(const float* __restrict__ cf) {
    size_t idx = (size_t)blockIdx.x * 256 + threadIdx.x;
    if (idx >= (size_t)OUTDIM * KDIM) return;
    int o = (int)(idx >> 15);            // KDIM = 2^15
    int k = (int)(idx & (KDIM - 1));
    int cs = k >> 14;
    int i  = (k >> 6) & (INPUTDIM - 1);
    int g  = k & (GRIDSZ - 1);
    float v = cf[(((size_t)cs * OUTDIM + o) * INPUTDIM + i) * GRIDSZ + g];
    __nv_bfloat16 h = __float2bfloat16(v);
    float hf = __bfloat162float(h);
    __nv_bfloat16 l = __float2bfloat16(v - hf);
    ((__nv_bfloat16*)g_Bhi)[idx] = h;
    ((__nv_bfloat16*)g_Blo)[idx] = l;
}

// ============================================================================
// Kernel 2: warp-specialized fused GEMM
//   128 CTAs (32 M x 4 N), 384 threads:
//     warps 0-3  : consumers — warp tile 32(M) x 64(N); A frags read ONCE
//     warps 4-11 : producers — feature-gen (1 sincosf + doubling seed,
//                  PRMT/truncation bf16 split) + B cp.async
// ============================================================================
__global__ void __launch_bounds__(NTHREADS, 1)
fourier_gemm(const float* __restrict__ x, const float* __restrict__ bias,
             float* __restrict__ out) {
    extern __shared__ char smem[];
    const uint32_t su32 = smem_to_u32(smem);
    const int tid = threadIdx.x;
    const int lid = tid & 31, wid = tid >> 5;
    const int mtile = blockIdx.x & (MTILES - 1);
    const int ntile = blockIdx.x >> 5;

    const uint32_t bar_full0  = su32 + SM_BAR;
    const uint32_t bar_full1  = su32 + SM_BAR + 8;
    const uint32_t bar_empty0 = su32 + SM_BAR + 16;
    const uint32_t bar_empty1 = su32 + SM_BAR + 24;

    if (tid == 0) {
        MBAR_INIT(bar_full0,  NPROD);
        MBAR_INIT(bar_full1,  NPROD);
        MBAR_INIT(bar_empty0, NCONS);
        MBAR_INIT(bar_empty1, NCONS);
    }
    __syncthreads();

    if (tid < NCONS) {
        // ==================== CONSUMER (warps 0-3) ====================
        const int wm = wid;                       // rows [wm*32, wm*32+32)
        const int mat = lid >> 3, mr = lid & 7;
        const uint32_t a_off =
            (uint32_t)((wm * 32 + (mat & 1) * 8 + mr) * ROWB + ((mat >> 1) * 8) * 2);
        const uint32_t b_off =
            (uint32_t)(((mat >> 1) * 8 + mr) * ROWB + ((mat & 1) * 8) * 2);

        float acc[2][8][4];
        #pragma unroll
        for (int mt = 0; mt < 2; ++mt)
            #pragma unroll
            for (int nt = 0; nt < 8; ++nt)
                #pragma unroll
                for (int q = 0; q < 4; ++q) acc[mt][nt][q] = 0.f;

        int phf0 = 0, phf1 = 0;
        for (int it = 0; it < NPAIR; ++it) {
            const int s = it & 1;
            if (s == 0) { MBAR_WAIT(bar_full0, phf0); phf0 ^= 1; }
            else        { MBAR_WAIT(bar_full1, phf1); phf1 ^= 1; }

            const uint32_t sbase = su32 + s * STAGEB;
            #pragma unroll
            for (int q = 0; q < 2; ++q) {          // q=0 cos, q=1 sin
                const uint32_t aHi = sbase + (q ? OFF_ASHI : OFF_ACHI) + a_off;
                const uint32_t aLo = sbase + (q ? OFF_ASLO : OFF_ACLO) + a_off;
                const uint32_t bHi = sbase + OFF_B0 + (q ? 2 * BBUF : 0) + b_off;
                const uint32_t bLo = bHi + BBUF;

                #pragma unroll
                for (int ks = 0; ks < 4; ++ks) {
                    const uint32_t ko = ks * 32;
                    uint32_t Ah[2][4], Al[2][4], Bh[4][4], Bl[4][4];
                    ldsm_x4(Ah[0], aHi + ko);
                    ldsm_x4(Ah[1], aHi + 16 * ROWB + ko);
                    #pragma unroll
                    for (int ng = 0; ng < 4; ++ng)
                        ldsm_x4(Bh[ng], bHi + ng * 16 * ROWB + ko);
                    #pragma unroll
                    for (int mt = 0; mt < 2; ++mt)
                        #pragma unroll
                        for (int ng = 0; ng < 4; ++ng) {
                            mma16816(acc[mt][ng * 2],     Ah[mt], Bh[ng][0], Bh[ng][1]);
                            mma16816(acc[mt][ng * 2 + 1], Ah[mt], Bh[ng][2], Bh[ng][3]);
                        }
                    #pragma unroll
                    for (int ng = 0; ng < 4; ++ng)
                        ldsm_x4(Bl[ng], bLo + ng * 16 * ROWB + ko);
                    #pragma unroll
                    for (int mt = 0; mt < 2; ++mt)
                        #pragma unroll
                        for (int ng = 0; ng < 4; ++ng) {
                            mma16816(acc[mt][ng * 2],     Ah[mt], Bl[ng][0], Bl[ng][1]);
                            mma16816(acc[mt][ng * 2 + 1], Ah[mt], Bl[ng][2], Bl[ng][3]);
                        }
                    ldsm_x4(Al[0], aLo + ko);
                    ldsm_x4(Al[1], aLo + 16 * ROWB + ko);
                    #pragma unroll
                    for (int mt = 0; mt < 2; ++mt)
                        #pragma unroll
                        for (int ng = 0; ng < 4; ++ng) {
                            mma16816(acc[mt][ng * 2],     Al[mt], Bh[ng][0], Bh[ng][1]);
                            mma16816(acc[mt][ng * 2 + 1], Al[mt], Bh[ng][2], Bh[ng][3]);
                        }
                }
            }
            MBAR_ARRIVE(s ? bar_empty1 : bar_empty0);
        }

        // ---- epilogue ----
        #pragma unroll
        for (int mt = 0; mt < 2; ++mt) {
            int r0 = mtile * MTILE + wm * 32 + mt * 16 + (lid >> 2);
            #pragma unroll
            for (int nt = 0; nt < 8; ++nt) {
                int c0 = ntile * NTILE + nt * 8 + (lid & 3) * 2;
                float b0 = __ldg(bias + c0);
                float b1 = __ldg(bias + c0 + 1);
                *(float2*)(out + (size_t)r0 * OUTDIM + c0) =
                    make_float2(acc[mt][nt][0] + b0, acc[mt][nt][1] + b1);
                *(float2*)(out + (size_t)(r0 + 8) * OUTDIM + c0) =
                    make_float2(acc[mt][nt][2] + b0, acc[mt][nt][3] + b1);
            }
        }
    } else {
        // ==================== PRODUCER (warps 4-11) ====================
        const int ptid = tid - NCONS;               // 0..255
        const int fb = ptid >> 1;                   // row 0..127
        const int g0 = (ptid & 1) * 32;             // 32 frequencies per thread
        const float* xrow = x + (size_t)(mtile * MTILE + fb) * INPUTDIM;
        const char* bhp = (const char*)g_Bhi;
        const char* blp = (const char*)g_Blo;

        int phe0 = 0, phe1 = 0;
        for (int it = 0; it < NPAIR; ++it) {
            const int s = it & 1;
            if (it >= NSTAGE) {
                if (s == 0) { MBAR_WAIT(bar_empty0, phe0); phe0 ^= 1; }
                else        { MBAR_WAIT(bar_empty1, phe1); phe1 ^= 1; }
            }
            const uint32_t sbase = su32 + s * STAGEB;

            // ---- B tiles: 4 buffers (cosHi,cosLo,sinHi,sinLo), 32 KB ----
            #pragma unroll
            for (int q = 0; q < 8; ++q) {
                int idx = ptid + q * 256;            // 0..2047 segs of 16B
                int buf = idx >> 9;                  // 0..3
                int r   = (idx >> 3) & 63;
                int seg = idx & 7;
                int c   = (buf >> 1) * NPAIR + it;   // cs*256 + i
                uint32_t dst = sbase + OFF_B0 + buf * BBUF + r * ROWB + seg * 16;
                const char* src = ((buf & 1) ? blp : bhp)
                    + (size_t)(ntile * NTILE + r) * (KDIM * 2)
                    + (size_t)c * 128 + seg * 16;
                cp_async16(dst, src);
            }
            asm volatile("cp.async.commit_group;" ::: "memory");

            // ---- A features: rotation fills cos AND sin, hi/lo split ----
            {
                float xv = __ldg(xrow + it);
                float S, C;
                sincosf(xv, &S, &C);
                float c0, s0;
                if (g0 == 0) { c0 = C; s0 = S; }
                else {
                    // angle 33*xv via 5 doublings (-> 32xv) + one rotation
                    float cd = C, sd = S;
                    #pragma unroll
                    for (int d = 0; d < 5; ++d) {
                        float s2 = 2.f * cd * sd;
                        float c2 = __fmaf_rn(2.f * cd, cd, -1.f);
                        cd = c2; sd = s2;
                    }
                    c0 = cd * C - sd * S;
                    s0 = sd * C + cd * S;
                }

                char* pch = smem + s * STAGEB + OFF_ACHI + fb * ROWB + g0 * 2;
                char* pcl = smem + s * STAGEB + OFF_ACLO + fb * ROWB + g0 * 2;
                char* psh = smem + s * STAGEB + OFF_ASHI + fb * ROWB + g0 * 2;
                char* psl = smem + s * STAGEB + OFF_ASLO + fb * ROWB + g0 * 2;

                #pragma unroll
                for (int jp = 0; jp < 16; ++jp) {
                    float vc0 = c0, vs0 = s0;
                    float c1 = c0 * C - s0 * S;
                    float s1 = s0 * C + c0 * S;
                    float vc1 = c1, vs1 = s1;
                    c0 = c1 * C - s1 * S;
                    s0 = s1 * C + c1 * S;

                    // cos pair: hi by truncation+PRMT, lo exact-residual bf16x2
                    uint32_t bc0 = __float_as_uint(vc0), bc1 = __float_as_uint(vc1);
                    uint32_t hcw = __byte_perm(bc0, bc1, 0x7632);
                    float hc0 = __uint_as_float(bc0 & 0xFFFF0000u);
                    float hc1 = __uint_as_float(bc1 & 0xFFFF0000u);
                    __nv_bfloat162 lcv = __floats2bfloat162_rn(vc0 - hc0, vc1 - hc1);
                    *(uint32_t*)(pch + jp * 4) = hcw;
                    *(uint32_t*)(pcl + jp * 4) = *(uint32_t*)&lcv;

                    // sin pair
                    uint32_t bs0 = __float_as_uint(vs0), bs1 = __float_as_uint(vs1);
                    uint32_t hsw = __byte_perm(bs0, bs1, 0x7632);
                    float hs0 = __uint_as_float(bs0 & 0xFFFF0000u);
                    float hs1 = __uint_as_float(bs1 & 0xFFFF0000u);
                    __nv_bfloat162 lsv = __floats2bfloat162_rn(vs0 - hs0, vs1 - hs1);
                    *(uint32_t*)(psh + jp * 4) = hsw;
                    *(uint32_t*)(psl + jp * 4) = *(uint32_t*)&lsv;
                }
            }

            asm volatile("cp.async.wait_group 0;" ::: "memory");
            MBAR_ARRIVE(s ? bar_full1 : bar_full0);
        }
    }
}

// ============================================================================
// Launch
// ============================================================================
extern "C" void kernel_launch(void* const* d_in, const int* in_sizes, int n_in,
                              void* d_out, int out_size) {
    const float* x    = (const float*)d_in[0];
    const float* cf   = (const float*)d_in[1];
    const float* bias = (const float*)d_in[2];
    float* out = (float*)d_out;

    cudaFuncSetAttribute(fourier_gemm,
                         cudaFuncAttributeMaxDynamicSharedMemorySize, SMEM_BYTES);

    prep_kernel<<<(OUTDIM * KDIM + 255) / 256, 256>>>(cf);
    fourier_gemm<<<MTILES * NTILES, NTHREADS, SMEM_BYTES>>>(x, bias, out);
    (void)in_sizes; (void)n_in; (void)out_size;
}

// round 8
// speedup vs baseline: 1.6409x; 1.0429x over previous
#include <cuda_runtime.h>
#include <cuda_bf16.h>
#include <cstdint>

// ============================================================================
// Problem constants
// ============================================================================
#define BATCH    4096
#define INPUTDIM 256
#define OUTDIM   256
#define GRIDSZ   64
#define KDIM     32768            // k = cs*16384 + i*64 + g
#define NPAIR    256              // loop over i; pair = (cos chunk i, sin chunk i)
#define MTILE    128
#define NTILE    64
#define MTILES   (BATCH / MTILE)  // 32
#define NTILES   (OUTDIM / NTILE) // 4
#define NTHREADS 384
#define NCONS    256              // consumer threads (warps 0-7, 2/SMSP via q-split)
#define NPROD    128              // producer threads (warps 8-11)

// SMEM stage: 4 A buffers (cosHi,cosLo,sinHi,sinLo) + 4 B buffers
#define ROWB     144
#define ABUF     (128 * ROWB)     // 18432
#define BBUF     (64 * ROWB)      // 9216
#define OFF_ACHI 0
#define OFF_ACLO (ABUF)
#define OFF_ASHI (2 * ABUF)
#define OFF_ASLO (3 * ABUF)
#define OFF_B0   (4 * ABUF)       // 4 contiguous B buffers: cHi,cLo,sHi,sLo
#define STAGEB   (4 * ABUF + 4 * BBUF)   // 110592
#define NSTAGE   2
#define SM_BAR   (NSTAGE * STAGEB)
#define SMEM_BYTES (NSTAGE * STAGEB + 64)

// ============================================================================
// Scratch (device globals — no allocation allowed)
// ============================================================================
__device__ uint4 g_Bhi[(size_t)OUTDIM * KDIM / 8];   // bf16 [256][32768] hi
__device__ uint4 g_Blo[(size_t)OUTDIM * KDIM / 8];   // bf16 [256][32768] lo

// ============================================================================
// Helpers
// ============================================================================
__device__ __forceinline__ uint32_t smem_to_u32(const void* p) {
    uint32_t a;
    asm("{ .reg .u64 t; cvta.to.shared.u64 t, %1; cvt.u32.u64 %0, t; }"
        : "=r"(a) : "l"(p));
    return a;
}

__device__ __forceinline__ void cp_async16(uint32_t dst, const void* src) {
    asm volatile("cp.async.cg.shared.global [%0], [%1], 16;"
                 :: "r"(dst), "l"(src) : "memory");
}

__device__ __forceinline__ void ldsm_x4(uint32_t r[4], uint32_t addr) {
    asm volatile("ldmatrix.sync.aligned.m8n8.x4.shared.b16 {%0,%1,%2,%3}, [%4];"
                 : "=r"(r[0]), "=r"(r[1]), "=r"(r[2]), "=r"(r[3]) : "r"(addr));
}

__device__ __forceinline__ void mma16816(float acc[4],
                                         const uint32_t a[4],
                                         uint32_t b0, uint32_t b1) {
    asm volatile(
        "mma.sync.aligned.m16n8k16.row.col.f32.bf16.bf16.f32 "
        "{%0,%1,%2,%3}, {%4,%5,%6,%7}, {%8,%9}, {%0,%1,%2,%3};"
        : "+f"(acc[0]), "+f"(acc[1]), "+f"(acc[2]), "+f"(acc[3])
        : "r"(a[0]), "r"(a[1]), "r"(a[2]), "r"(a[3]), "r"(b0), "r"(b1));
}

#define MBAR_INIT(addr, cnt) \
    asm volatile("mbarrier.init.shared.b64 [%0], %1;" \
                 :: "r"((uint32_t)(addr)), "r"((uint32_t)(cnt)) : "memory")

#define MBAR_ARRIVE(addr) \
    asm volatile("mbarrier.arrive.shared.b64 _, [%0];" \
                 :: "r"((uint32_t)(addr)) : "memory")

#define MBAR_WAIT(addr, parity) do { \
    uint32_t _m = (uint32_t)(addr), _p = (uint32_t)(parity), _d; \
    asm volatile( \
        "{\n\t.reg .pred p;\n\t" \
        "mbarrier.try_wait.parity.acquire.cta.shared::cta.b64 p, [%1], %2;\n\t" \
        "selp.b32 %0, 1, 0, p;\n\t}" \
        : "=r"(_d) : "r"(_m), "r"(_p) : "memory"); \
    if (!_d) { \
        asm volatile( \
            "{\n\t.reg .pred P1;\n\t" \
            "WL_%=:\n\t" \
            "mbarrier.try_wait.parity.acquire.cta.shared::cta.b64 P1, [%0], %1, 0x989680;\n\t" \
            "@P1 bra.uni WD_%=;\n\t" \
            "bra.uni WL_%=;\n\t" \
            "WD_%=:\n\t}" \
            :: "r"(_m), "r"(_p) : "memory"); \
    } \
} while (0)

// ============================================================================
// Kernel 1: prep — fouriercoeffs[2,O,I,G] f32 -> K-major bf16 hi/lo scratch
// ============================================================================
__global__ void prep_kernel(const float* __restrict__ cf) {
    size_t idx = (size_t)blockIdx.x * 256 + threadIdx.x;
    if (idx >= (size_t)OUTDIM * KDIM) return;
    int o = (int)(idx >> 15);            // KDIM = 2^15
    int k = (int)(idx & (KDIM - 1));
    int cs = k >> 14;
    int i  = (k >> 6) & (INPUTDIM - 1);
    int g  = k & (GRIDSZ - 1);
    float v = cf[(((size_t)cs * OUTDIM + o) * INPUTDIM + i) * GRIDSZ + g];
    __nv_bfloat16 h = __float2bfloat16(v);
    float hf = __bfloat162float(h);
    __nv_bfloat16 l = __float2bfloat16(v - hf);
    ((__nv_bfloat16*)g_Bhi)[idx] = h;
    ((__nv_bfloat16*)g_Blo)[idx] = l;
}

// ============================================================================
// Kernel 2: warp-specialized fused GEMM, q-split consumers
//   128 CTAs (32 M x 4 N), 384 threads:
//     warps 0-7  : consumers — warp (wm, wq): 32(M) x 64(N), cos OR sin half
//     warps 8-11 : producers — thread=row, 64-step rotation, STS.128
//   Epilogue: bar.sync BEFORE scratch reuse (fixes R7 consumer-consumer race)
// ============================================================================
__global__ void __launch_bounds__(NTHREADS, 1)
fourier_gemm(const float* __restrict__ x, const float* __restrict__ bias,
             float* __restrict__ out) {
    extern __shared__ char smem[];
    const uint32_t su32 = smem_to_u32(smem);
    const int tid = threadIdx.x;
    const int lid = tid & 31, wid = tid >> 5;
    const int mtile = blockIdx.x & (MTILES - 1);
    const int ntile = blockIdx.x >> 5;

    const uint32_t bar_full0  = su32 + SM_BAR;
    const uint32_t bar_full1  = su32 + SM_BAR + 8;
    const uint32_t bar_empty0 = su32 + SM_BAR + 16;
    const uint32_t bar_empty1 = su32 + SM_BAR + 24;

    if (tid == 0) {
        MBAR_INIT(bar_full0,  NPROD);
        MBAR_INIT(bar_full1,  NPROD);
        MBAR_INIT(bar_empty0, NCONS);
        MBAR_INIT(bar_empty1, NCONS);
    }
    __syncthreads();

    if (tid < NCONS) {
        // ==================== CONSUMER (warps 0-7) ====================
        const int wm = wid & 3;                   // SMSP / M-row group
        const int wq = wid >> 2;                  // 0 = cos half, 1 = sin half
        const int mat = lid >> 3, mr = lid & 7;
        const uint32_t a_off =
            (uint32_t)((wm * 32 + (mat & 1) * 8 + mr) * ROWB + ((mat >> 1) * 8) * 2);
        const uint32_t b_off =
            (uint32_t)(((mat >> 1) * 8 + mr) * ROWB + ((mat & 1) * 8) * 2);

        const uint32_t offAH = wq ? OFF_ASHI : OFF_ACHI;
        const uint32_t offAL = wq ? OFF_ASLO : OFF_ACLO;
        const uint32_t offBH = OFF_B0 + (wq ? 2 * BBUF : 0);

        float acc[2][8][4];
        #pragma unroll
        for (int mt = 0; mt < 2; ++mt)
            #pragma unroll
            for (int nt = 0; nt < 8; ++nt)
                #pragma unroll
                for (int q = 0; q < 4; ++q) acc[mt][nt][q] = 0.f;

        int phf0 = 0, phf1 = 0;
        for (int it = 0; it < NPAIR; ++it) {
            const int s = it & 1;
            if (s == 0) { MBAR_WAIT(bar_full0, phf0); phf0 ^= 1; }
            else        { MBAR_WAIT(bar_full1, phf1); phf1 ^= 1; }

            const uint32_t sbase = su32 + s * STAGEB;
            const uint32_t aHi = sbase + offAH + a_off;
            const uint32_t aLo = sbase + offAL + a_off;
            const uint32_t bHi = sbase + offBH + b_off;
            const uint32_t bLo = bHi + BBUF;

            #pragma unroll
            for (int ks = 0; ks < 4; ++ks) {
                const uint32_t ko = ks * 32;
                uint32_t Ah[2][4], Al[2][4], Bh[4][4], Bl[4][4];
                ldsm_x4(Ah[0], aHi + ko);
                ldsm_x4(Ah[1], aHi + 16 * ROWB + ko);
                #pragma unroll
                for (int ng = 0; ng < 4; ++ng)
                    ldsm_x4(Bh[ng], bHi + ng * 16 * ROWB + ko);
                #pragma unroll
                for (int mt = 0; mt < 2; ++mt)
                    #pragma unroll
                    for (int ng = 0; ng < 4; ++ng) {
                        mma16816(acc[mt][ng * 2],     Ah[mt], Bh[ng][0], Bh[ng][1]);
                        mma16816(acc[mt][ng * 2 + 1], Ah[mt], Bh[ng][2], Bh[ng][3]);
                    }
                #pragma unroll
                for (int ng = 0; ng < 4; ++ng)
                    ldsm_x4(Bl[ng], bLo + ng * 16 * ROWB + ko);
                #pragma unroll
                for (int mt = 0; mt < 2; ++mt)
                    #pragma unroll
                    for (int ng = 0; ng < 4; ++ng) {
                        mma16816(acc[mt][ng * 2],     Ah[mt], Bl[ng][0], Bl[ng][1]);
                        mma16816(acc[mt][ng * 2 + 1], Ah[mt], Bl[ng][2], Bl[ng][3]);
                    }
                ldsm_x4(Al[0], aLo + ko);
                ldsm_x4(Al[1], aLo + 16 * ROWB + ko);
                #pragma unroll
                for (int mt = 0; mt < 2; ++mt)
                    #pragma unroll
                    for (int ng = 0; ng < 4; ++ng) {
                        mma16816(acc[mt][ng * 2],     Al[mt], Bh[ng][0], Bh[ng][1]);
                        mma16816(acc[mt][ng * 2 + 1], Al[mt], Bh[ng][2], Bh[ng][3]);
                    }
            }
            MBAR_ARRIVE(s ? bar_empty1 : bar_empty0);
        }

        // ---- epilogue: merge cos-half + sin-half via smem scratch ----
        // RACE FIX: all consumer warps must finish their stage reads before
        // the stage-0 region is reused as scratch.
        asm volatile("bar.sync 1, %0;" :: "n"(NCONS) : "memory");
        {
            const int fl = wm * 32 + lid;
            float* scr = (float*)(smem) + (size_t)fl * 68;
            if (wq == 1) {
                #pragma unroll
                for (int mt = 0; mt < 2; ++mt)
                    #pragma unroll
                    for (int nt = 0; nt < 8; ++nt)
                        *(float4*)(scr + (mt * 8 + nt) * 4) =
                            make_float4(acc[mt][nt][0], acc[mt][nt][1],
                                        acc[mt][nt][2], acc[mt][nt][3]);
            }
            asm volatile("bar.sync 1, %0;" :: "n"(NCONS) : "memory");
            if (wq == 0) {
                #pragma unroll
                for (int mt = 0; mt < 2; ++mt) {
                    int r0 = mtile * MTILE + wm * 32 + mt * 16 + (lid >> 2);
                    #pragma unroll
                    for (int nt = 0; nt < 8; ++nt) {
                        float4 o2 = *(float4*)(scr + (mt * 8 + nt) * 4);
                        int c0 = ntile * NTILE + nt * 8 + (lid & 3) * 2;
                        float b0 = __ldg(bias + c0);
                        float b1 = __ldg(bias + c0 + 1);
                        *(float2*)(out + (size_t)r0 * OUTDIM + c0) =
                            make_float2(acc[mt][nt][0] + o2.x + b0,
                                        acc[mt][nt][1] + o2.y + b1);
                        *(float2*)(out + (size_t)(r0 + 8) * OUTDIM + c0) =
                            make_float2(acc[mt][nt][2] + o2.z + b0,
                                        acc[mt][nt][3] + o2.w + b1);
                    }
                }
            }
        }
    } else {
        // ==================== PRODUCER (warps 8-11) ====================
        const int ptid = tid - NCONS;               // 0..127 == row
        const int fb = ptid;
        const float* xrow = x + (size_t)(mtile * MTILE + fb) * INPUTDIM;
        const char* bhp = (const char*)g_Bhi;
        const char* blp = (const char*)g_Blo;

        int phe0 = 0, phe1 = 0;
        for (int it = 0; it < NPAIR; ++it) {
            const int s = it & 1;
            if (it >= NSTAGE) {
                if (s == 0) { MBAR_WAIT(bar_empty0, phe0); phe0 ^= 1; }
                else        { MBAR_WAIT(bar_empty1, phe1); phe1 ^= 1; }
            }
            const uint32_t sbase = su32 + s * STAGEB;

            // ---- B tiles: 4 buffers (cosHi,cosLo,sinHi,sinLo), 32 KB ----
            #pragma unroll
            for (int q = 0; q < 16; ++q) {
                int idx = ptid + q * NPROD;          // 0..2047 segs of 16B
                int buf = idx >> 9;                  // 0..3
                int r   = (idx >> 3) & 63;
                int seg = idx & 7;
                int c   = (buf >> 1) * NPAIR + it;   // cs*256 + i
                uint32_t dst = sbase + OFF_B0 + buf * BBUF + r * ROWB + seg * 16;
                const char* src = ((buf & 1) ? blp : bhp)
                    + (size_t)(ntile * NTILE + r) * (KDIM * 2)
                    + (size_t)c * 128 + seg * 16;
                cp_async16(dst, src);
            }
            asm volatile("cp.async.commit_group;" ::: "memory");

            // ---- A features: 64-step rotation, hi/lo split, STS.128 ----
            {
                float xv = __ldg(xrow + it);
                float S, C;
                sincosf(xv, &S, &C);
                float c0 = C, s0 = S;               // freq 1

                char* pch = smem + s * STAGEB + OFF_ACHI + fb * ROWB;
                char* pcl = smem + s * STAGEB + OFF_ACLO + fb * ROWB;
                char* psh = smem + s * STAGEB + OFF_ASHI + fb * ROWB;
                char* psl = smem + s * STAGEB + OFF_ASLO + fb * ROWB;

                #pragma unroll
                for (int w = 0; w < 8; ++w) {
                    uint32_t wch[4], wcl[4], wsh[4], wsl[4];
                    #pragma unroll
                    for (int p = 0; p < 4; ++p) {
                        float vc0 = c0, vs0 = s0;
                        float c1 = c0 * C - s0 * S;
                        float s1 = s0 * C + c0 * S;
                        float vc1 = c1, vs1 = s1;
                        c0 = c1 * C - s1 * S;
                        s0 = s1 * C + c1 * S;

                        uint32_t bc0 = __float_as_uint(vc0);
                        uint32_t bc1 = __float_as_uint(vc1);
                        wch[p] = __byte_perm(bc0, bc1, 0x7632);
                        float hc0 = __uint_as_float(bc0 & 0xFFFF0000u);
                        float hc1 = __uint_as_float(bc1 & 0xFFFF0000u);
                        __nv_bfloat162 lcv =
                            __floats2bfloat162_rn(vc0 - hc0, vc1 - hc1);
                        wcl[p] = *(uint32_t*)&lcv;

                        uint32_t bs0 = __float_as_uint(vs0);
                        uint32_t bs1 = __float_as_uint(vs1);
                        wsh[p] = __byte_perm(bs0, bs1, 0x7632);
                        float hs0 = __uint_as_float(bs0 & 0xFFFF0000u);
                        float hs1 = __uint_as_float(bs1 & 0xFFFF0000u);
                        __nv_bfloat162 lsv =
                            __floats2bfloat162_rn(vs0 - hs0, vs1 - hs1);
                        wsl[p] = *(uint32_t*)&lsv;
                    }
                    *(uint4*)(pch + w * 16) = make_uint4(wch[0], wch[1], wch[2], wch[3]);
                    *(uint4*)(pcl + w * 16) = make_uint4(wcl[0], wcl[1], wcl[2], wcl[3]);
                    *(uint4*)(psh + w * 16) = make_uint4(wsh[0], wsh[1], wsh[2], wsh[3]);
                    *(uint4*)(psl + w * 16) = make_uint4(wsl[0], wsl[1], wsl[2], wsl[3]);
                }
            }

            asm volatile("cp.async.wait_group 0;" ::: "memory");
            MBAR_ARRIVE(s ? bar_full1 : bar_full0);
        }
    }
}

// ============================================================================
// Launch
// ============================================================================
extern "C" void kernel_launch(void* const* d_in, const int* in_sizes, int n_in,
                              void* d_out, int out_size) {
    const float* x    = (const float*)d_in[0];
    const float* cf   = (const float*)d_in[1];
    const float* bias = (const float*)d_in[2];
    float* out = (float*)d_out;

    cudaFuncSetAttribute(fourier_gemm,
                         cudaFuncAttributeMaxDynamicSharedMemorySize, SMEM_BYTES);

    prep_kernel<<<(OUTDIM * KDIM + 255) / 256, 256>>>(cf);
    fourier_gemm<<<MTILES * NTILES, NTHREADS, SMEM_BYTES>>>(x, bias, out);
    (void)in_sizes; (void)n_in; (void)out_size;
}